// round 10
// baseline (speedup 1.0000x reference)
#include <cuda_runtime.h>

#define NEGV    -1.0e8f
#define BH      8                 // band height (rows per CTA) = cells per warp
#define NB      128               // number of bands
#define GW      1025              // boundary row: columns 0..1024
#define NGROUPS 258               // 258 groups x 4 steps = 1032; last active s=1030

// G[b][j] = V[8b][j] over 4 states. Row 128 = final row i=1024. ~2.1 MB.
__device__ float4 G[(NB + 1) * GW];
// PROG[b*32] = highest column j published into G[b]. Padded: 1 line per band.
__device__ int PROG[(NB + 1) * 32];

// ---------------------------------------------------------------------------
__global__ void init_kernel() {
    int i = threadIdx.x;
    if (i <= NB) PROG[i * 32] = 0;
}

// ---------------------------------------------------------------------------
__device__ __forceinline__ int ldacq(const int* p) {
    int v;
    asm volatile("ld.acquire.gpu.s32 %0, [%1];" : "=r"(v) : "l"(p) : "memory");
    return v;
}
__device__ __forceinline__ void strel(int* p, int v) {
    asm volatile("st.release.gpu.s32 [%0], %1;" :: "l"(p), "r"(v) : "memory");
}
// Plain coherent 16B global load (NOT .nc: G is written by peer CTAs).
__device__ __forceinline__ float4 ldg4(const float4* p) {
    float4 v;
    asm volatile("ld.global.v4.f32 {%0,%1,%2,%3}, [%4];"
                 : "=f"(v.x), "=f"(v.y), "=f"(v.z), "=f"(v.w) : "l"(p) : "memory");
    return v;
}

// ---------------------------------------------------------------------------
// Persistent band DP, ONE WARP per band. Grid = 128 blocks x 32 threads.
// Lane = 4*a + t : cell a (row within band, 0..7), target state t (m,x,y,s).
// Cell a computes column j = s - a + 1 at step s (active for s in [a, a+1023]).
// smem D slots: slot a+1 = cell a (slot 0 unused). Sources at step s:
//   up (t=1): Pm1[a]  left (t=2): Pm1[a+1]  diag (t=0,3): Pm2[a]
// Cell a==0 takes up/diag from the halo ring: Hr[p & 7] = V[8b][p],
//   diag = halo(s), up = halo(s+1). Ring refilled 4 columns per group.
// ---------------------------------------------------------------------------
__global__ __launch_bounds__(32) void dp_kernel(const float* __restrict__ theta,
                                                const float4* __restrict__ A4) {
    __shared__ float4 D[3][BH + 2];
    __shared__ float4 Hr[8];                   // halo ring, slot = p & 7

    const int b   = blockIdx.x;
    const int tid = threadIdx.x;
    const int a   = tid >> 2;
    const int t   = tid & 3;
    const int r   = BH * b + a;                // theta/A row = i-1
    const float4 NEG4 = make_float4(NEGV, NEGV, NEGV, NEGV);
    const float4* Grow = G + b * GW;                   // top boundary (read; b>0)
    float*        Gout = (float*)(G + (b + 1) * GW);   // bottom row (write)
    const int*    Pin  = PROG + b * 32;
    int*          Pout = PROG + (b + 1) * 32;

    if (tid < 3 * (BH + 2)) ((float4*)D)[tid] = NEG4;  // left halo + pre-active

    // A/theta register ring, depth 8: slot k holds data for step s, s&7==k.
    float4 Ar[8]; float Tr[8];
    #pragma unroll
    for (int k = 0; k < 8; ++k) {
        int col = k - a; col = col < 0 ? 0 : col;
        int idx = (r * 1024 + col) * 4 + t;
        Ar[k] = __ldg(A4 + idx);
        Tr[k] = __ldg(theta + idx);
    }

    // Preloop: fill halo positions 0..4 (slots 0..4).
    //   halo(0) = V[8b][0]: band 0 -> THE SEED (0,0,0,0); else NEG (col-0 bound).
    //   halo(p>=1): band 0 -> NEG; else G[b][p] after watermark >= 4.
    if (b == 0) {
        if (tid == 0) Hr[0] = make_float4(0.f, 0.f, 0.f, 0.f);
        if (tid >= 1 && tid <= 4) Hr[tid] = NEG4;
    } else {
        int av = 0;
        while (av < 4) av = ldacq(Pin);
        if (tid == 0) Hr[0] = NEG4;
        if (tid >= 1 && tid <= 4) Hr[tid] = ldg4(Grow + tid);
    }
    __syncwarp();

    const bool bot     = (a == BH - 1);
    const bool topCell = (a == 0) && (t != 2);
    const bool relLane = (tid == 4 * (BH - 1));        // a=7, t=0

    float4* Pn  = D[0];
    float4* Pm1 = D[2];
    float4* Pm2 = D[1];

    for (int g = 0; g < NGROUPS; ++g) {
        // Group prologue (g>=1): ensure halos 4g+1..4g+4 are in the ring.
        if (g > 0) {
            int base = 4 * g;
            if (b != 0) {
                int need = base + 4; need = need > 1024 ? 1024 : need;
                int av = 0;
                while (av < need) av = ldacq(Pin);
                if (tid < 4) {
                    int p  = base + 1 + tid;
                    int pc = p > 1024 ? 1024 : p;
                    Hr[p & 7] = ldg4(Grow + pc);
                }
            } else {
                if (tid < 4) Hr[(base + 1 + tid) & 7] = NEG4;
            }
            __syncwarp();
        }

        #pragma unroll
        for (int k = 0; k < 4; ++k) {
            const int s = 4 * g + k;
            float4 av = Ar[s & 7];
            float  tv = Tr[s & 7];

            float4 s4;
            if (topCell) {
                s4 = (t == 1) ? Hr[(s + 1) & 7]        // up   = halo(s+1)
                              : Hr[s & 7];             // diag = halo(s)
            } else {
                const float4* sp = (t == 1) ? (Pm1 + a)
                                 : (t == 2) ? (Pm1 + a + 1)
                                            : (Pm2 + a);
                s4 = *sp;
            }

            float w0 = s4.x + av.x;
            float w1 = s4.y + av.y;
            float w2 = s4.z + av.z;
            float w3 = s4.w + av.w;
            float m = fmaxf(fmaxf(w0, w1), fmaxf(w2, w3));
            float sum = __expf(w0 - m) + __expf(w1 - m) +
                        __expf(w2 - m) + __expf(w3 - m);
            float res = m + __logf(sum) + tv;

            bool active = (s >= a) && (s <= a + 1023);
            if (active) {
                ((float*)(Pn + a + 1))[t] = res;
                if (bot) Gout[(s - (BH - 2)) * 4 + t] = res;   // col j = s-6
            }

            // refill A/theta ring for step s+8
            {
                int col = s + 8 - a;
                col = col < 0 ? 0 : (col > 1023 ? 1023 : col);
                int idx = (r * 1024 + col) * 4 + t;
                Ar[s & 7] = __ldg(A4 + idx);
                Tr[s & 7] = __ldg(theta + idx);
            }

            __syncwarp();   // orders smem writes + bottom-row stores (warp scope)

            // one release per group, after the syncwarp that orders lanes 28-31
            if (k == 3 && relLane) {
                int jmax = s - (BH - 2);
                if (jmax >= 1) strel(Pout, jmax > 1024 ? 1024 : jmax);
            }

            float4* tmp = Pm2; Pm2 = Pm1; Pm1 = Pn; Pn = tmp;
        }
    }
}

// ---------------------------------------------------------------------------
// Stream-ordered after dp_kernel: plain read is safe.
__global__ void final_kernel(float* out) {
    float4 v = ldg4(G + NB * GW + 1024);               // V[1024][1024]
    float m = fmaxf(fmaxf(v.x, v.y), fmaxf(v.z, v.w));
    out[0] = m + __logf(__expf(v.x - m) + __expf(v.y - m) +
                        __expf(v.z - m) + __expf(v.w - m));
}

// ---------------------------------------------------------------------------
extern "C" void kernel_launch(void* const* d_in, const int* in_sizes, int n_in,
                              void* d_out, int out_size) {
    const float*  theta = (const float*)d_in[0];   // [1024,1024,4]
    const float4* A4    = (const float4*)d_in[1];  // [1024,1024,4,4]

    init_kernel<<<1, 256>>>();
    dp_kernel<<<NB, 32>>>(theta, A4);
    final_kernel<<<1, 1>>>((float*)d_out);
}

// round 12
// speedup vs baseline: 1.1149x; 1.1149x over previous
#include <cuda_runtime.h>

#define NEGV  -1.0e8f
#define WPC   4                  // warp-bands per CTA (8 rows each)
#define NCTA  32                 // 32 CTAs x 32 rows = 1024 rows
#define GW    1025               // boundary row: columns 0..1024
#define NGRP  258                // 258 groups x 4 steps = 1032; last active s=1030

// G[B][j] = V[32B][j] over 4 states (CTA-to-CTA boundary rows).
__device__ float4 G[(NCTA + 1) * GW];
// PROG[B*32] = highest column published into G[B]. Padded: 1 line per entry.
__device__ int PROG[(NCTA + 1) * 32];

// ---------------------------------------------------------------------------
__global__ void init_kernel() {
    int i = threadIdx.x;
    if (i <= NCTA) PROG[i * 32] = 0;
}

// ---------------------------------------------------------------------------
__device__ __forceinline__ int ldacq_gpu(const int* p) {
    int v;
    asm volatile("ld.acquire.gpu.s32 %0, [%1];" : "=r"(v) : "l"(p) : "memory");
    return v;
}
__device__ __forceinline__ void strel_gpu(int* p, int v) {
    asm volatile("st.release.gpu.s32 [%0], %1;" :: "l"(p), "r"(v) : "memory");
}
__device__ __forceinline__ int ldacq_cta(const int* p) {
    int v;
    asm volatile("ld.acquire.cta.s32 %0, [%1];" : "=r"(v) : "l"(p) : "memory");
    return v;
}
__device__ __forceinline__ void strel_cta(int* p, int v) {
    asm volatile("st.release.cta.s32 [%0], %1;" :: "l"(p), "r"(v) : "memory");
}
// Plain coherent 16B global load (NOT .nc: G is written by peer CTAs).
__device__ __forceinline__ float4 ldg4(const float4* p) {
    float4 v;
    asm volatile("ld.global.v4.f32 {%0,%1,%2,%3}, [%4];"
                 : "=f"(v.x), "=f"(v.y), "=f"(v.z), "=f"(v.w) : "l"(p) : "memory");
    return v;
}

// ---------------------------------------------------------------------------
// Hierarchical persistent band DP. Grid = 32 CTAs x 128 threads (4 warps).
// Warp w handles rows 32B + 8w + 1 .. +8. Lane = 4*a + t (cell a, state t).
// Cell a computes column j = s - a + 1 at step s (active s in [a, a+1023]).
// Engine (proven rounds 7/8/10): smem diag buffers Pn/Pm1/Pm2, slot a+1=cell a.
//   up (t=1): Pm1[a]  left (t=2): Pm1[a+1]  diag (t=0,3): Pm2[a]
// Cell a==0 reads halos: warp0 from H0 ring (global/constants); warps 1-3
// directly from producer warp's HS ring (halo(p) at slot p & 63).
// ---------------------------------------------------------------------------
__global__ __launch_bounds__(128) void dp_kernel(const float* __restrict__ theta,
                                                 const float4* __restrict__ A4) {
    __shared__ float4 D[WPC][3][10];       // per-warp diagonal buffers
    __shared__ float4 HS[WPC - 1][64];     // warp w bottom row ring (w=0..2)
    __shared__ float4 H0[32];              // warp 0 halo ring (from global)
    __shared__ int    WSf[3];              // producer watermark (cols published)
    __shared__ int    CWf[3];              // consumer progress (cols consumed)

    const int B    = blockIdx.x;
    const int tid  = threadIdx.x;
    const int w    = tid >> 5;
    const int lane = tid & 31;
    const int a    = lane >> 2;
    const int t    = lane & 3;
    const int r    = 32 * B + 8 * w + a;               // theta/A row = i-1
    const float4 NEG4 = make_float4(NEGV, NEGV, NEGV, NEGV);
    const float4* Grow = G + B * GW;                   // top boundary (warp0)
    float*        Gout = (float*)(G + (B + 1) * GW);   // bottom row (warp3)
    const int*    Pin  = PROG + B * 32;
    int*          Pout = PROG + (B + 1) * 32;

    // ---- smem init (only CTA-wide barrier in the kernel) ----
    if (tid < WPC * 3 * 10) ((float4*)D)[tid] = NEG4;  // left halo + pre-active
    if (tid < 3) { HS[tid][0] = NEG4; WSf[tid] = 0; CWf[tid] = 0; }
    if (tid >= 64 && tid < 96) H0[tid - 64] = NEG4;
    if (tid == 0 && B == 0) H0[0] = make_float4(0.f, 0.f, 0.f, 0.f);  // SEED
    __syncthreads();

    // ---- A/theta register ring, depth 8: slot k = data for step s, s&7==k ----
    float4 Ar[8]; float Tr[8];
    #pragma unroll
    for (int k = 0; k < 8; ++k) {
        int col = k - a; col = col < 0 ? 0 : col;
        int idx = (r * 1024 + col) * 4 + t;
        Ar[k] = __ldg(A4 + idx);
        Tr[k] = __ldg(theta + idx);
    }

    // ---- warp0 preload: halo cols 1..8 (groups 0,1); slot 0 preset ----
    if (w == 0) {
        if (B > 0) {
            int av = 0; while (av < 8) av = ldacq_gpu(Pin);
            if (lane < 8) H0[lane + 1] = ldg4(Grow + lane + 1);
        }
        __syncwarp();
    }

    const bool bot      = (a == 7);
    const bool topCell  = (a == 0) && (t != 2);
    const bool flagLane = (lane == 28);                // a=7, t=0

    float4* Pn  = &D[w][0][0];
    float4* Pm1 = &D[w][2][0];
    float4* Pm2 = &D[w][1][0];

    for (int g = 0; g < NGRP; ++g) {
        // ---------- group prologue ----------
        if (w == 0) {
            // prefetch halos for group g+2 (cols 4g+9..4g+12), 2 groups ahead
            int cbase = 4 * g + 9;
            if (cbase <= 1024) {
                if (B > 0) {
                    int need = 4 * g + 12; need = need > 1024 ? 1024 : need;
                    int av = 0; while (av < need) av = ldacq_gpu(Pin);
                    if (lane < 4) {
                        int p = cbase + lane, pc = p > 1024 ? 1024 : p;
                        H0[p & 31] = ldg4(Grow + pc);
                    }
                } else {
                    if (lane < 4) H0[(cbase + lane) & 31] = NEG4;
                }
            }
            __syncwarp();
        } else {
            // wait until producer warp published cols up to 4g+4
            int need = 4 * g + 4; need = need > 1024 ? 1024 : need;
            while (ldacq_cta(&WSf[w - 1]) < need) {}
            __syncwarp();
        }

        // ---------- 4 DP steps ----------
        #pragma unroll
        for (int k = 0; k < 4; ++k) {
            const int s = 4 * g + k;
            float4 av = Ar[s & 7];
            float  tv = Tr[s & 7];

            float4 s4;
            if (topCell) {
                if (w == 0) s4 = (t == 1) ? H0[(s + 1) & 31] : H0[s & 31];
                else        s4 = (t == 1) ? HS[w - 1][(s + 1) & 63]
                                          : HS[w - 1][s & 63];
            } else {
                const float4* sp = (t == 1) ? (Pm1 + a)
                                 : (t == 2) ? (Pm1 + a + 1)
                                            : (Pm2 + a);
                s4 = *sp;
            }

            float w0 = s4.x + av.x;
            float w1 = s4.y + av.y;
            float w2 = s4.z + av.z;
            float w3 = s4.w + av.w;
            float m = fmaxf(fmaxf(w0, w1), fmaxf(w2, w3));
            float sum = __expf(w0 - m) + __expf(w1 - m) +
                        __expf(w2 - m) + __expf(w3 - m);
            float res = m + __logf(sum) + tv;

            bool active = (s >= a) && (s <= a + 1023);
            if (active) {
                ((float*)(Pn + a + 1))[t] = res;
                if (bot) {                           // column j = s - 6 (>=1)
                    int j = s - 6;
                    if (w == 3) Gout[j * 4 + t] = res;            // global row
                    else ((float*)&HS[w][j & 63])[t] = res;       // smem ring
                }
            }

            // refill A/theta ring for step s+8
            {
                int col = s + 8 - a;
                col = col < 0 ? 0 : (col > 1023 ? 1023 : col);
                int idx = (r * 1024 + col) * 4 + t;
                Ar[s & 7] = __ldg(A4 + idx);
                Tr[s & 7] = __ldg(theta + idx);
            }

            __syncwarp();   // orders all lanes' smem/global stores (hb to flags)

            float4* tmp = Pm2; Pm2 = Pm1; Pm1 = Pn; Pn = tmp;
        }

        // ---------- group epilogue: publish / backpressure ----------
        int jmax = 4 * g - 3;                        // last col stored this group
        if (w < 3) {
            if (flagLane && jmax >= 1)
                strel_cta(&WSf[w], jmax > 1024 ? 1024 : jmax);
            // ring backpressure: next group writes cols up to 4g+1; the slot of
            // col j holds col j-64 until overwrite -> need CW >= j-63.
            int limit = (4 * g + 1) - 60;
            if (limit > 0) {
                while (((volatile int*)CWf)[w] < limit) {}
            }
        } else {
            if (flagLane && (g & 1) && jmax >= 1)
                strel_gpu(Pout, jmax > 1024 ? 1024 : jmax);       // every 8 cols
        }
        if (w >= 1 && flagLane) {
            int c = 4 * g + 4;                       // cols consumed through g
            ((volatile int*)CWf)[w - 1] = c > 1024 ? 1024 : c;
        }
        __syncwarp();
    }
}

// ---------------------------------------------------------------------------
// Stream-ordered after dp_kernel: plain read is safe.
__global__ void final_kernel(float* out) {
    float4 v = ldg4(G + NCTA * GW + 1024);           // V[1024][1024]
    float m = fmaxf(fmaxf(v.x, v.y), fmaxf(v.z, v.w));
    out[0] = m + __logf(__expf(v.x - m) + __expf(v.y - m) +
                        __expf(v.z - m) + __expf(v.w - m));
}

// ---------------------------------------------------------------------------
extern "C" void kernel_launch(void* const* d_in, const int* in_sizes, int n_in,
                              void* d_out, int out_size) {
    const float*  theta = (const float*)d_in[0];   // [1024,1024,4]
    const float4* A4    = (const float4*)d_in[1];  // [1024,1024,4,4]

    init_kernel<<<1, 64>>>();
    dp_kernel<<<NCTA, 128>>>(theta, A4);
    final_kernel<<<1, 1>>>((float*)d_out);
}

// round 13
// speedup vs baseline: 2.7262x; 2.4452x over previous
#include <cuda_runtime.h>

#define NEGV  -1.0e8f
#define BH    32                 // band height (rows per CTA)
#define NB    32                 // number of bands
#define GW    1025               // boundary row: columns 0..1024
#define NGRP  132                // 132 groups x 8 steps = 1056; last active s=1054

// G[b][j] = V[32b][j] over 4 states. Row 32 = final row i=1024.
__device__ float4 G[(NB + 1) * GW];
// PROG[b*32] = highest column published into G[b]. Padded: one line per band.
__device__ int PROG[(NB + 1) * 32];

// ---------------------------------------------------------------------------
__global__ void init_kernel() {
    int i = threadIdx.x;
    if (i <= NB) PROG[i * 32] = 0;
}

// ---------------------------------------------------------------------------
__device__ __forceinline__ int ldacq_gpu(const int* p) {
    int v;
    asm volatile("ld.acquire.gpu.s32 %0, [%1];" : "=r"(v) : "l"(p) : "memory");
    return v;
}
__device__ __forceinline__ void strel_gpu(int* p, int v) {
    asm volatile("st.release.gpu.s32 [%0], %1;" :: "l"(p), "r"(v) : "memory");
}
// Plain coherent 16B global load (NOT .nc: G is written by peer CTAs).
__device__ __forceinline__ float4 ldg4(const float4* p) {
    float4 v;
    asm volatile("ld.global.v4.f32 {%0,%1,%2,%3}, [%4];"
                 : "=f"(v.x), "=f"(v.y), "=f"(v.z), "=f"(v.w) : "l"(p) : "memory");
    return v;
}
#define BAR_DP() asm volatile("bar.sync 1, 128;" ::: "memory")

// ---------------------------------------------------------------------------
// Persistent band DP with a dedicated halo warp.
// Grid = 32 CTAs x 160 threads. Threads 0..127 (warps 0-3): DP engine,
// thread = 4*a + t (cell a = row in band 0..31, target state t). Threads
// 128..159 (warp 4): halo prefetch into ring H[32] (col p at slot p&31).
// Cell a computes column j = s - a + 1 at step s (active s in [a, a+1023]).
// Engine (round-8-proven): smem diag buffers, slot a+1 = cell a.
//   up (t=1): Pm1[a]  left (t=2): Pm1[a+1]  diag (t=0,3): Pm2[a]
// Cell a==0 (t!=2) reads halos straight from the ring:
//   diag = H[s&31], up = H[(s+1)&31].
// Group g = steps 8g..8g+7 consumes halo cols 8g..8g+8; halo warp fetches
// cols 8g+9..8g+16 during group g (distinct ring slots mod 32).
// ---------------------------------------------------------------------------
__global__ __launch_bounds__(160) void dp_kernel(const float* __restrict__ theta,
                                                 const float4* __restrict__ A4) {
    __shared__ float4 D[3][BH + 2];
    __shared__ float4 H[32];

    const int B    = blockIdx.x;
    const int tid  = threadIdx.x;
    const float4 NEG4 = make_float4(NEGV, NEGV, NEGV, NEGV);
    const float4* Grow = G + B * GW;                   // top boundary (read)
    float*        Gout = (float*)(G + (B + 1) * GW);   // bottom row (write)
    const int*    Pin  = PROG + B * 32;
    int*          Pout = PROG + (B + 1) * 32;

    if (tid < 3 * (BH + 2)) ((float4*)D)[tid] = NEG4;  // left halo + pre-active

    if (tid >= 128) {
        // ===================== HALO WARP =====================
        const int lane = tid - 128;
        // Preload ring cols 0..8 for group 0.
        if (B == 0) {
            if (lane <= 8)
                H[lane] = (lane == 0) ? make_float4(0.f, 0.f, 0.f, 0.f)  // SEED
                                      : NEG4;
        } else {
            if (lane == 0) { int av = 0; while (av < 8) av = ldacq_gpu(Pin); }
            __syncwarp();
            if (lane <= 8)
                H[lane] = (lane == 0) ? NEG4 : ldg4(Grow + lane);
        }
        __syncthreads();                               // ring ready for group 0

        for (int g = 0; g < NGRP; ++g) {
            int base = 8 * g + 9;                      // fetch cols base..base+7
            if (base <= 1024) {
                if (B != 0) {
                    int need = base + 7; need = need > 1024 ? 1024 : need;
                    if (lane == 0) { int av = 0; while (av < need) av = ldacq_gpu(Pin); }
                    __syncwarp();                      // hb: acquire -> loads
                    if (lane < 8) {
                        int p = base + lane;
                        int pc = p > 1024 ? 1024 : p;
                        H[p & 31] = ldg4(Grow + pc);
                    }
                } else {
                    if (lane < 8) H[(base + lane) & 31] = NEG4;
                }
            }
            __syncthreads();                           // hand ring to DP warps
        }
        return;
    }

    // ===================== DP THREADS (0..127) =====================
    const int a = tid >> 2;
    const int t = tid & 3;
    const int r = BH * B + a;                          // theta/A row = i-1
    const bool bot      = (a == BH - 1);               // threads 124..127
    const bool topCell  = (a == 0) && (t != 2);
    const bool relLane  = (tid == 4 * (BH - 1));       // thread 124

    // A/theta register ring, depth 8: slot k holds data for step s, s&7==k.
    float4 Ar[8]; float Tr[8];
    #pragma unroll
    for (int k = 0; k < 8; ++k) {
        int col = k - a; col = col < 0 ? 0 : col;
        int idx = (r * 1024 + col) * 4 + t;
        Ar[k] = __ldg(A4 + idx);
        Tr[k] = __ldg(theta + idx);
    }

    __syncthreads();                                   // initial ring ready

    float4* Pn  = D[0];
    float4* Pm1 = D[2];
    float4* Pm2 = D[1];

    for (int g = 0; g < NGRP; ++g) {
        #pragma unroll
        for (int k = 0; k < 8; ++k) {
            const int s = 8 * g + k;
            float4 av = Ar[k];
            float  tv = Tr[k];

            float4 s4;
            if (topCell) {
                s4 = (t == 1) ? H[(s + 1) & 31]        // up   = halo(s+1)
                              : H[s & 31];             // diag = halo(s)
            } else {
                const float4* sp = (t == 1) ? (Pm1 + a)
                                 : (t == 2) ? (Pm1 + a + 1)
                                            : (Pm2 + a);
                s4 = *sp;
            }

            float w0 = s4.x + av.x;
            float w1 = s4.y + av.y;
            float w2 = s4.z + av.z;
            float w3 = s4.w + av.w;
            float m = fmaxf(fmaxf(w0, w1), fmaxf(w2, w3));
            float sum = __expf(w0 - m) + __expf(w1 - m) +
                        __expf(w2 - m) + __expf(w3 - m);
            float res = m + __logf(sum) + tv;

            bool active = (s >= a) && (s <= a + 1023);
            if (active) {
                ((float*)(Pn + a + 1))[t] = res;
                if (bot) Gout[(s - (BH - 2)) * 4 + t] = res;   // col j = s-30
            }

            // refill A/theta ring for step s+8
            {
                int col = s + 8 - a;
                col = col < 0 ? 0 : (col > 1023 ? 1023 : col);
                int idx = (r * 1024 + col) * 4 + t;
                Ar[k] = __ldg(A4 + idx);
                Tr[k] = __ldg(theta + idx);
            }

            if (k < 7) BAR_DP();                       // DP-warps-only barrier
            else       __syncthreads();                // group end: all 160

            float4* tmp = Pm2; Pm2 = Pm1; Pm1 = Pn; Pn = tmp;
        }

        // One release per group, ordered after the group-end __syncthreads
        // (barrier establishes hb over all DP warps' Gout stores this group).
        if (relLane) {
            int jmax = 8 * g + 7 - (BH - 2);           // = 8g - 23
            if (jmax >= 1) strel_gpu(Pout, jmax > 1024 ? 1024 : jmax);
        }
    }
}

// ---------------------------------------------------------------------------
// Stream-ordered after dp_kernel: plain read is safe.
__global__ void final_kernel(float* out) {
    float4 v = ldg4(G + NB * GW + 1024);               // V[1024][1024]
    float m = fmaxf(fmaxf(v.x, v.y), fmaxf(v.z, v.w));
    out[0] = m + __logf(__expf(v.x - m) + __expf(v.y - m) +
                        __expf(v.z - m) + __expf(v.w - m));
}

// ---------------------------------------------------------------------------
extern "C" void kernel_launch(void* const* d_in, const int* in_sizes, int n_in,
                              void* d_out, int out_size) {
    const float*  theta = (const float*)d_in[0];   // [1024,1024,4]
    const float4* A4    = (const float4*)d_in[1];  // [1024,1024,4,4]

    init_kernel<<<1, 64>>>();
    dp_kernel<<<NB, 160>>>(theta, A4);
    final_kernel<<<1, 1>>>((float*)d_out);
}